// round 2
// baseline (speedup 1.0000x reference)
#include <cuda_runtime.h>
#include <cstdint>

#define NN 100000
#define EE 800000

// ---------------- scratch (__device__ globals; no allocation allowed) ----------
__device__ float g_deg[NN];                       // degree -> dinv_sqrt (in place)
__device__ __align__(16) float g_agg[NN * 128];   // aggregated X (layer-1 input to GEMM)
__device__ __align__(16) float g_h2[NN * 40];     // hidden @ W2 (pre-aggregation)
__device__ unsigned g_mask[1600000];              // 51.2M dropout keep-bits

// ---------------- small helpers ------------------------------------------------
__device__ __forceinline__ unsigned long long pack2(float x, float y) {
    unsigned long long r;
    asm("mov.b64 %0, {%1, %2};" : "=l"(r) : "f"(x), "f"(y));
    return r;
}
__device__ __forceinline__ float2 unpack2(unsigned long long v) {
    float2 r;
    asm("mov.b64 {%0, %1}, %2;" : "=f"(r.x), "=f"(r.y) : "l"(v));
    return r;
}
__device__ __forceinline__ unsigned long long fma2(unsigned long long a,
                                                   unsigned long long b,
                                                   unsigned long long c) {
    unsigned long long d;
    asm("fma.rn.f32x2 %0, %1, %2, %3;" : "=l"(d) : "l"(a), "l"(b), "l"(c));
    return d;
}
__device__ __forceinline__ void red4(float* p, float a, float b, float c, float d) {
    asm volatile("red.global.add.v4.f32 [%0], {%1,%2,%3,%4};"
                 :: "l"(p), "f"(a), "f"(b), "f"(c), "f"(d) : "memory");
}

// JAX threefry2x32 with key = (0, 42)  [jax.random.key(42)]
__device__ __forceinline__ void threefry42(unsigned& x0, unsigned& x1) {
    const unsigned ks0 = 0u, ks1 = 42u, ks2 = 0x1BD11BDAu ^ 42u;
    x0 += ks0; x1 += ks1;
#define TFR(r) { x0 += x1; x1 = (x1 << (r)) | (x1 >> (32 - (r))); x1 ^= x0; }
    TFR(13) TFR(15) TFR(26) TFR(6)   x0 += ks1; x1 += ks2 + 1u;
    TFR(17) TFR(29) TFR(16) TFR(24)  x0 += ks2; x1 += ks0 + 2u;
    TFR(13) TFR(15) TFR(26) TFR(6)   x0 += ks0; x1 += ks1 + 3u;
    TFR(17) TFR(29) TFR(16) TFR(24)  x0 += ks1; x1 += ks2 + 4u;
    TFR(13) TFR(15) TFR(26) TFR(6)   x0 += ks2; x1 += ks0 + 5u;
#undef TFR
}

// ---------------- degree / normalization --------------------------------------
__global__ void deg_init_kernel() {
    int i = blockIdx.x * blockDim.x + threadIdx.x;
    if (i < NN) g_deg[i] = 1.0f;   // self loop
}
__global__ void deg_scatter_kernel(const int* __restrict__ dst) {
    int e = blockIdx.x * blockDim.x + threadIdx.x;
    if (e < EE) atomicAdd(&g_deg[dst[e]], 1.0f);
}
__global__ void deg_fin_kernel() {
    int i = blockIdx.x * blockDim.x + threadIdx.x;
    if (i < NN) g_deg[i] = rsqrtf(g_deg[i]);   // now holds dinv_sqrt
}

// ---------------- dropout mask: JAX *partitionable* threefry -------------------
// For element linear index i (< 2^32): counter = (hi=0, lo=i),
// bits = out0 ^ out1, keep <=> MSB(bits)==0  (uniform<0.5 via [1,2) bitcast).
__global__ void mask_kernel() {
    unsigned t = blockIdx.x * blockDim.x + threadIdx.x;
    if (t >= 1600000u) return;
    unsigned base = t * 32u;
    unsigned w = 0u;
#pragma unroll 8
    for (int j = 0; j < 32; j++) {
        unsigned x0 = 0u;
        unsigned x1 = base + (unsigned)j;
        threefry42(x0, x1);
        w |= ((~(x0 ^ x1)) >> 31) << j;
    }
    g_mask[t] = w;
}

// ---------------- layer-1 aggregation: g_agg = D^-1/2 (A+I) D^-1/2 X -----------
__global__ void agg1_init_kernel(const float* __restrict__ x) {
    int gid = blockIdx.x * blockDim.x + threadIdx.x;   // over NN*32 float4s
    if (gid >= NN * 32) return;
    int node = gid >> 5;
    float di = g_deg[node];
    float s = di * di;
    float4 v = reinterpret_cast<const float4*>(x)[gid];
    float4 o = make_float4(v.x * s, v.y * s, v.z * s, v.w * s);
    reinterpret_cast<float4*>(g_agg)[gid] = o;
}
__global__ void agg1_scatter_kernel(const float* __restrict__ x,
                                    const int* __restrict__ src,
                                    const int* __restrict__ dst) {
    int gid = blockIdx.x * blockDim.x + threadIdx.x;
    int e = gid >> 5, lane = gid & 31;
    if (e >= EE) return;
    int s = src[e], d = dst[e];
    float nrm = g_deg[s] * g_deg[d];
    float4 v = *reinterpret_cast<const float4*>(&x[s * 128 + lane * 4]);
    red4(&g_agg[d * 128 + lane * 4], v.x * nrm, v.y * nrm, v.z * nrm, v.w * nrm);
}

// ---------------- GEMM1: H = relu(g_agg @ W1 + b1) * dropout ------------------
// 128x128 block tile, 256 threads, 8x8 thread tile, packed f32x2 FMA.
__global__ __launch_bounds__(256) void gemm1_kernel(const float* __restrict__ W,
                                                    const float* __restrict__ bias,
                                                    float* __restrict__ H) {
    __shared__ __align__(16) float As[32][132];   // [k][m]
    __shared__ __align__(16) float Bs[32][128];   // [k][n]
    const int t = threadIdx.x;
    const int tx = t & 15, ty = t >> 4;
    const int m0 = blockIdx.x * 128;
    const int n0 = blockIdx.y * 128;

    unsigned long long acc[8][4];
#pragma unroll
    for (int i = 0; i < 8; i++)
#pragma unroll
        for (int j = 0; j < 4; j++) acc[i][j] = 0ull;

    const int am = t >> 3;    // 0..31 row-in-pass (A load)
    const int akq = t & 7;    // float4 index in k (A load)
    const int wk = t >> 5;    // 0..7 k-row-in-pass (W load)
    const int wn = t & 31;    // float4 col (W load)

    for (int kc = 0; kc < 4; kc++) {
        // A tile (transposed into As[k][m])
#pragma unroll
        for (int p = 0; p < 4; p++) {
            int m = p * 32 + am;
            int gr = m0 + m;
            float4 v = make_float4(0.f, 0.f, 0.f, 0.f);
            if (gr < NN)
                v = *reinterpret_cast<const float4*>(&g_agg[gr * 128 + kc * 32 + akq * 4]);
            As[akq * 4 + 0][m] = v.x;
            As[akq * 4 + 1][m] = v.y;
            As[akq * 4 + 2][m] = v.z;
            As[akq * 4 + 3][m] = v.w;
        }
        // W tile
#pragma unroll
        for (int p = 0; p < 4; p++) {
            int k = p * 8 + wk;
            *reinterpret_cast<float4*>(&Bs[k][wn * 4]) =
                *reinterpret_cast<const float4*>(&W[(kc * 32 + k) * 512 + n0 + wn * 4]);
        }
        __syncthreads();
#pragma unroll
        for (int k = 0; k < 32; k++) {
            float4 a0 = *reinterpret_cast<const float4*>(&As[k][ty * 4]);
            float4 a1 = *reinterpret_cast<const float4*>(&As[k][ty * 4 + 64]);
            ulonglong2 b0 = *reinterpret_cast<const ulonglong2*>(&Bs[k][tx * 4]);
            ulonglong2 b1 = *reinterpret_cast<const ulonglong2*>(&Bs[k][tx * 4 + 64]);
            unsigned long long ad[8];
            ad[0] = pack2(a0.x, a0.x); ad[1] = pack2(a0.y, a0.y);
            ad[2] = pack2(a0.z, a0.z); ad[3] = pack2(a0.w, a0.w);
            ad[4] = pack2(a1.x, a1.x); ad[5] = pack2(a1.y, a1.y);
            ad[6] = pack2(a1.z, a1.z); ad[7] = pack2(a1.w, a1.w);
#pragma unroll
            for (int i = 0; i < 8; i++) {
                acc[i][0] = fma2(ad[i], b0.x, acc[i][0]);
                acc[i][1] = fma2(ad[i], b0.y, acc[i][1]);
                acc[i][2] = fma2(ad[i], b1.x, acc[i][2]);
                acc[i][3] = fma2(ad[i], b1.y, acc[i][3]);
            }
        }
        __syncthreads();
    }

    // epilogue: bias + relu + dropout (mask bits) -> H
    float4 bias0 = *reinterpret_cast<const float4*>(&bias[n0 + tx * 4]);
    float4 bias1 = *reinterpret_cast<const float4*>(&bias[n0 + 64 + tx * 4]);
    const int w0i = (n0 + tx * 4) >> 5;
    const int w1i = (n0 + 64 + tx * 4) >> 5;
    const int sh = (tx * 4) & 31;
#pragma unroll
    for (int i = 0; i < 8; i++) {
        int rl = (i < 4) ? (ty * 4 + i) : (64 + ty * 4 + (i - 4));
        int row = m0 + rl;
        if (row >= NN) continue;
        unsigned mw0 = g_mask[row * 16 + w0i];
        unsigned mw1 = g_mask[row * 16 + w1i];
        float2 c0 = unpack2(acc[i][0]);
        float2 c1 = unpack2(acc[i][1]);
        float2 c2 = unpack2(acc[i][2]);
        float2 c3 = unpack2(acc[i][3]);
        float4 o0, o1;
        o0.x = ((mw0 >> (sh + 0)) & 1u) ? fmaxf(c0.x + bias0.x, 0.f) * 2.f : 0.f;
        o0.y = ((mw0 >> (sh + 1)) & 1u) ? fmaxf(c0.y + bias0.y, 0.f) * 2.f : 0.f;
        o0.z = ((mw0 >> (sh + 2)) & 1u) ? fmaxf(c1.x + bias0.z, 0.f) * 2.f : 0.f;
        o0.w = ((mw0 >> (sh + 3)) & 1u) ? fmaxf(c1.y + bias0.w, 0.f) * 2.f : 0.f;
        o1.x = ((mw1 >> (sh + 0)) & 1u) ? fmaxf(c2.x + bias1.x, 0.f) * 2.f : 0.f;
        o1.y = ((mw1 >> (sh + 1)) & 1u) ? fmaxf(c2.y + bias1.y, 0.f) * 2.f : 0.f;
        o1.z = ((mw1 >> (sh + 2)) & 1u) ? fmaxf(c3.x + bias1.z, 0.f) * 2.f : 0.f;
        o1.w = ((mw1 >> (sh + 3)) & 1u) ? fmaxf(c3.y + bias1.w, 0.f) * 2.f : 0.f;
        *reinterpret_cast<float4*>(&H[row * 512 + n0 + tx * 4]) = o0;
        *reinterpret_cast<float4*>(&H[row * 512 + n0 + 64 + tx * 4]) = o1;
    }
}

// ---------------- GEMM2: g_h2 = H @ W2  (100000x512 @ 512x40) ------------------
__global__ __launch_bounds__(256) void gemm2_kernel(const float* __restrict__ H,
                                                    const float* __restrict__ W2) {
    __shared__ __align__(16) float As[32][260];
    __shared__ __align__(16) float Ws[32][40];
    const int t = threadIdx.x;
    const int rg = t & 63;        // row group 0..63
    const int cg = t >> 6;        // col group 0..3 (10 cols each)
    const int m0 = blockIdx.x * 256;

    unsigned long long acc[4][5];
#pragma unroll
    for (int i = 0; i < 4; i++)
#pragma unroll
        for (int j = 0; j < 5; j++) acc[i][j] = 0ull;

    const int akq = t & 7;
    const int am = t >> 3;   // 0..31 per pass

    for (int kc = 0; kc < 16; kc++) {
#pragma unroll
        for (int p = 0; p < 8; p++) {
            int m = p * 32 + am;
            int gr = m0 + m;
            float4 v = make_float4(0.f, 0.f, 0.f, 0.f);
            if (gr < NN)
                v = *reinterpret_cast<const float4*>(&H[gr * 512 + kc * 32 + akq * 4]);
            As[akq * 4 + 0][m] = v.x;
            As[akq * 4 + 1][m] = v.y;
            As[akq * 4 + 2][m] = v.z;
            As[akq * 4 + 3][m] = v.w;
        }
#pragma unroll
        for (int p = 0; p < 2; p++) {
            int idx = p * 256 + t;
            if (idx < 320) {
                int k = idx / 10, c = idx % 10;
                *reinterpret_cast<float4*>(&Ws[k][c * 4]) =
                    *reinterpret_cast<const float4*>(&W2[(kc * 32 + k) * 40 + c * 4]);
            }
        }
        __syncthreads();
#pragma unroll
        for (int k = 0; k < 32; k++) {
            float4 a = *reinterpret_cast<const float4*>(&As[k][rg * 4]);
            const float* wr = &Ws[k][cg * 10];
            unsigned long long w0 = *reinterpret_cast<const unsigned long long*>(wr + 0);
            unsigned long long w1 = *reinterpret_cast<const unsigned long long*>(wr + 2);
            unsigned long long w2 = *reinterpret_cast<const unsigned long long*>(wr + 4);
            unsigned long long w3 = *reinterpret_cast<const unsigned long long*>(wr + 6);
            unsigned long long w4 = *reinterpret_cast<const unsigned long long*>(wr + 8);
            float av[4] = {a.x, a.y, a.z, a.w};
#pragma unroll
            for (int i = 0; i < 4; i++) {
                unsigned long long ai = pack2(av[i], av[i]);
                acc[i][0] = fma2(ai, w0, acc[i][0]);
                acc[i][1] = fma2(ai, w1, acc[i][1]);
                acc[i][2] = fma2(ai, w2, acc[i][2]);
                acc[i][3] = fma2(ai, w3, acc[i][3]);
                acc[i][4] = fma2(ai, w4, acc[i][4]);
            }
        }
        __syncthreads();
    }
#pragma unroll
    for (int i = 0; i < 4; i++) {
        int row = m0 + rg * 4 + i;
        if (row >= NN) continue;
#pragma unroll
        for (int j = 0; j < 5; j++)
            *reinterpret_cast<unsigned long long*>(&g_h2[row * 40 + cg * 10 + j * 2]) = acc[i][j];
    }
}

// ---------------- layer-2 aggregation: out = Â g_h2 + b2 -----------------------
__global__ void agg2_init_kernel(const float* __restrict__ b2, float* __restrict__ out) {
    int gid = blockIdx.x * blockDim.x + threadIdx.x;   // over NN*10 float4s
    if (gid >= NN * 10) return;
    int node = gid / 10;
    int c = gid - node * 10;
    float di = g_deg[node];
    float s = di * di;
    float4 v = *reinterpret_cast<const float4*>(&g_h2[node * 40 + c * 4]);
    float4 bb = *reinterpret_cast<const float4*>(&b2[c * 4]);
    float4 o = make_float4(bb.x + v.x * s, bb.y + v.y * s, bb.z + v.z * s, bb.w + v.w * s);
    *reinterpret_cast<float4*>(&out[node * 40 + c * 4]) = o;
}
__global__ void agg2_scatter_kernel(const int* __restrict__ src,
                                    const int* __restrict__ dst,
                                    float* __restrict__ out) {
    int gid = blockIdx.x * blockDim.x + threadIdx.x;   // EE*10
    int e = gid / 10;
    int c = gid - e * 10;
    if (e >= EE) return;
    int s = src[e], d = dst[e];
    float nrm = g_deg[s] * g_deg[d];
    float4 v = *reinterpret_cast<const float4*>(&g_h2[s * 40 + c * 4]);
    red4(&out[d * 40 + c * 4], v.x * nrm, v.y * nrm, v.z * nrm, v.w * nrm);
}

// ---------------- launch --------------------------------------------------------
extern "C" void kernel_launch(void* const* d_in, const int* in_sizes, int n_in,
                              void* d_out, int out_size) {
    const float* x  = (const float*)d_in[0];
    const int*   ei = (const int*)d_in[1];
    const float* W1 = (const float*)d_in[2];
    const float* b1 = (const float*)d_in[3];
    const float* W2 = (const float*)d_in[4];
    const float* b2 = (const float*)d_in[5];
    (void)in_sizes; (void)n_in; (void)out_size;

    float* out = (float*)d_out;           // [NN, 40]
    float* hidden = out + NN * 40;        // [NN, 512]
    const int* src = ei;
    const int* dst = ei + EE;

    deg_init_kernel<<<(NN + 255) / 256, 256>>>();
    deg_scatter_kernel<<<(EE + 255) / 256, 256>>>(dst);
    deg_fin_kernel<<<(NN + 255) / 256, 256>>>();

    mask_kernel<<<(1600000 + 255) / 256, 256>>>();

    agg1_init_kernel<<<(NN * 32) / 256, 256>>>(x);
    agg1_scatter_kernel<<<(EE * 32) / 256, 256>>>(x, src, dst);

    gemm1_kernel<<<dim3((NN + 127) / 128, 4), 256>>>(W1, b1, hidden);
    gemm2_kernel<<<(NN + 255) / 256, 256>>>(hidden, W2);

    agg2_init_kernel<<<(NN * 10 + 255) / 256, 256>>>(b2, out);
    agg2_scatter_kernel<<<(EE * 10) / 256, 256>>>(src, dst, out);
}